// round 11
// baseline (speedup 1.0000x reference)
#include <cuda_runtime.h>
#include <cuda_bf16.h>
#include <math.h>

#define BATCH 512
#define NCAM  6
#define NID   751
#define DIM   2048
#define D2    (DIM/2)       /* 1024 packed bf16x2 words per row */
#define CN    (NCAM*NID)    /* 4506 */
#define BC    (BATCH*NCAM)  /* 3072 */
#define NK    (D2/16)       /* 64 k-blocks of 16 words (32 halves) */

// ---------------- scratch (device globals; no allocation allowed) ----------
__device__ float    g_F[BATCH*DIM];       // normalized features (fp32, scatter)
__device__ unsigned g_Fh[BATCH*D2];       // packed bf16x2, K-permuted
__device__ unsigned g_Ah[CN*D2];          // packed bf16x2, K-permuted
__device__ float    g_sumZ[BC];           // sum exp(logits) per (b,cam)
__device__ unsigned long long g_rank_key[BC];
__device__ unsigned long long g_back_key[BC];
__device__ int      g_rank_idx[BC];
__device__ float    g_score[BC];
__device__ int      g_qidx[BATCH];
__device__ int      g_cam[BATCH];
__device__ int      g_lab[BATCH];
__device__ int      g_tasks[NCAM*BC];
__device__ int      g_cnt[NCAM];
__device__ float    g_loss;
__device__ unsigned g_done;

// ---------------- helpers --------------------------------------------------
__device__ __forceinline__ unsigned fenc(float f){
    unsigned u = __float_as_uint(f);
    return (u & 0x80000000u) ? ~u : (u | 0x80000000u);
}
__device__ __forceinline__ float fdec(unsigned e){
    unsigned u = (e & 0x80000000u) ? (e ^ 0x80000000u) : ~e;
    return __uint_as_float(u);
}
__device__ __forceinline__ int scal_int(const void* p){
    int v = *(const int*)p;
    if (v > -1000000 && v < 1000000) return v;
    return (int)(*(const float*)p);
}
__device__ __forceinline__ float scal_float(const void* p){
    int v = *(const int*)p;
    if (v > -1000000 && v < 1000000) return (float)v;
    return *(const float*)p;
}
__device__ __forceinline__ unsigned pack_bf2(float x, float y){
    __nv_bfloat162 h = __floats2bfloat162_rn(x, y);
    return *(unsigned*)&h;
}
// K-permutation inside each 16-word chunk: fragment words contiguous per thread
__device__ __forceinline__ int permk2(int K){
    return (K & ~15) | ((K & 3) << 2) | ((K >> 2) & 3);
}
__device__ __forceinline__ void cpasync16(unsigned saddr, const void* g){
    asm volatile("cp.async.cg.shared.global [%0], [%1], 16;" :: "r"(saddr), "l"(g));
}

// ---------------- feature norm + setup (fused) ------------------------------
__global__ __launch_bounds__(256) void k_norm_feat(const float* __restrict__ in,
                                                   const int* __restrict__ labels,
                                                   const int* __restrict__ cams){
    int row = blockIdx.x;
    int tid = threadIdx.x;
    int gi = row*256 + tid;
    if(gi < BC){ g_rank_key[gi]=0ull; g_back_key[gi]=0ull; g_sumZ[gi]=0.0f; }
    if(gi < NCAM) g_cnt[gi]=0;
    if(gi == 0){ g_loss = 0.0f; g_done = 0u; }
    if(gi < BATCH){
        int cam = cams[gi]-1, lab = labels[gi]-1;
        g_cam[gi]=cam; g_lab[gi]=lab;
        g_qidx[gi]=cam*NID+lab;
    }
    const float4* ip = (const float4*)(in + (size_t)row*DIM);
    float4 a = ip[tid], b = ip[tid+256];
    float ss = a.x*a.x+a.y*a.y+a.z*a.z+a.w*a.w
             + b.x*b.x+b.y*b.y+b.z*b.z+b.w*b.w;
    __shared__ float red[8];
    #pragma unroll
    for(int o=16;o;o>>=1) ss += __shfl_xor_sync(0xffffffffu, ss, o);
    if((tid&31)==0) red[tid>>5]=ss;
    __syncthreads();
    float tot = red[0]+red[1]+red[2]+red[3]+red[4]+red[5]+red[6]+red[7];
    float s = 1.0f/(sqrtf(tot)+1e-12f);
    a.x*=s;a.y*=s;a.z*=s;a.w*=s; b.x*=s;b.y*=s;b.z*=s;b.w*=s;
    float4* op = (float4*)(g_F + (size_t)row*DIM);
    op[tid]=a; op[tid+256]=b;
    unsigned* hp = g_Fh + (size_t)row*D2;
    hp[permk2(2*tid  )]     = pack_bf2(a.x,a.y);
    hp[permk2(2*tid+1)]     = pack_bf2(a.z,a.w);
    hp[permk2(512+2*tid  )] = pack_bf2(b.x,b.y);
    hp[permk2(512+2*tid+1)] = pack_bf2(b.z,b.w);
}

// cross/intra anchors: packed bf16 + output base (fused warm path)
__global__ __launch_bounds__(256) void k_norm_cross(const float* __restrict__ cross,
                                                    const float* __restrict__ intra,
                                                    const void* epp,
                                                    float* __restrict__ out){
    int row = blockIdx.x;
    int tid = threadIdx.x;
    bool warm = (scal_int(epp) <= 10);
    const float* in = warm ? intra : cross;
    const float4* ip = (const float4*)(in + (size_t)row*DIM);
    float4 a = ip[tid], b = ip[tid+256];
    float ss = a.x*a.x+a.y*a.y+a.z*a.z+a.w*a.w
             + b.x*b.x+b.y*b.y+b.z*b.z+b.w*b.w;
    __shared__ float red[8];
    #pragma unroll
    for(int o=16;o;o>>=1) ss += __shfl_xor_sync(0xffffffffu, ss, o);
    if((tid&31)==0) red[tid>>5]=ss;
    __syncthreads();
    float tot = red[0]+red[1]+red[2]+red[3]+red[4]+red[5]+red[6]+red[7];
    float s = 1.0f/(sqrtf(tot)+1e-12f);
    a.x*=s;a.y*=s;a.z*=s;a.w*=s; b.x*=s;b.y*=s;b.z*=s;b.w*=s;
    unsigned* hp = g_Ah + (size_t)row*D2;
    hp[permk2(2*tid  )]     = pack_bf2(a.x,a.y);
    hp[permk2(2*tid+1)]     = pack_bf2(a.z,a.w);
    hp[permk2(512+2*tid  )] = pack_bf2(b.x,b.y);
    hp[permk2(512+2*tid+1)] = pack_bf2(b.z,b.w);
    // out+1 is only 4B aligned -> scalar stores
    float* dst = out + 1 + (size_t)row*DIM;
    dst[tid*4+0]=a.x; dst[tid*4+1]=a.y; dst[tid*4+2]=a.z; dst[tid*4+3]=a.w;
    dst[1024+tid*4+0]=b.x; dst[1024+tid*4+1]=b.y; dst[1024+tid*4+2]=b.z; dst[1024+tid*4+3]=b.w;
}

// ---------------- main GEMM (bf16 mma, 3-stage cp.async pipeline) -----------
// logits CTAs (by<4) fold sum-exp directly (logits in [-1,1]: no max needed);
// rank CTAs (by>=4) fold argmax keys. Logits never materialized.
#define MMA_OP(ACC,A0,A1,A2,A3,B0,B1) \
    asm volatile("mma.sync.aligned.m16n8k16.row.col.f32.bf16.bf16.f32 " \
        "{%0,%1,%2,%3}, {%4,%5,%6,%7}, {%8,%9}, {%0,%1,%2,%3};" \
        : "+f"((ACC)[0]), "+f"((ACC)[1]), "+f"((ACC)[2]), "+f"((ACC)[3]) \
        : "r"(A0),"r"(A1),"r"(A2),"r"(A3),"r"(B0),"r"(B1))

__global__ __launch_bounds__(256,2) void k_gemm_main(){
    __shared__ unsigned As[3][2048];    // [stage][row*16 + word]
    __shared__ unsigned Bs[3][2048];

    int tid=threadIdx.x, bx=blockIdx.x, by=blockIdx.y;
    bool rankmode = (by >= 4);

    int lane = tid & 31, w = tid >> 5;
    int wm = w >> 1, wn = w & 1;
    int g = lane >> 2, tig = lane & 3;
    int m0 = wm*32, n0 = wn*64;

    // per-thread prefetch lanes: 2 A rows + 2 B rows, one 16B seg each
    int prow = tid >> 2, pseg = tid & 3;
    int ar0 = by*128 + prow;
    const unsigned* gA0 = (rankmode ? (g_Ah + (size_t)g_qidx[ar0-512]*D2)
                                    : (g_Fh + (size_t)ar0*D2)) + pseg*4;
    const unsigned* gA1 = (rankmode ? (g_Ah + (size_t)g_qidx[ar0-512+64]*D2)
                                    : (g_Fh + (size_t)(ar0+64)*D2)) + pseg*4;
    int cb0 = bx*128 + prow;      int cc0 = (cb0 < CN) ? cb0 : (CN-1);
    int cb1 = cb0 + 64;           int cc1 = (cb1 < CN) ? cb1 : (CN-1);
    const unsigned* gB0 = g_Ah + (size_t)cc0*D2 + pseg*4;
    const unsigned* gB1 = g_Ah + (size_t)cc1*D2 + pseg*4;
    unsigned off0 = (unsigned)((prow*16 + pseg*4)*4);
    unsigned off1 = (unsigned)(((prow+64)*16 + pseg*4)*4);
    unsigned sbA = (unsigned)__cvta_generic_to_shared(&As[0][0]);
    unsigned sbB = (unsigned)__cvta_generic_to_shared(&Bs[0][0]);

    float acc[2][8][4];
    #pragma unroll
    for(int mi=0;mi<2;mi++)
        #pragma unroll
        for(int ni=0;ni<8;ni++)
            #pragma unroll
            for(int q=0;q<4;q++) acc[mi][ni][q]=0.0f;

    // prefetch stages 0 and 1
    #pragma unroll
    for(int st=0; st<2; st++){
        unsigned bo = (unsigned)(st*8192);
        int ko = st*16;
        cpasync16(sbA + bo + off0, gA0 + ko);
        cpasync16(sbA + bo + off1, gA1 + ko);
        cpasync16(sbB + bo + off0, gB0 + ko);
        cpasync16(sbB + bo + off1, gB1 + ko);
        asm volatile("cp.async.commit_group;" ::: "memory");
    }
    asm volatile("cp.async.wait_group 1;" ::: "memory");
    __syncthreads();

    int s = 0;
    for(int kb=0; kb<NK; kb++){
        const unsigned* as  = As[s];
        const unsigned* bsp = Bs[s];

        uint4 a_lo[2], a_hi[2];
        #pragma unroll
        for(int mi=0;mi<2;mi++){
            a_lo[mi] = *(const uint4*)(as + (m0 + mi*16 + g)*16 + tig*4);
            a_hi[mi] = *(const uint4*)(as + (m0 + mi*16 + 8 + g)*16 + tig*4);
        }
        #pragma unroll
        for(int nh=0; nh<2; nh++){
            uint4 bf[4];
            #pragma unroll
            for(int nj=0;nj<4;nj++)
                bf[nj] = *(const uint4*)(bsp + (n0 + (nh*4+nj)*8 + g)*16 + tig*4);
            #pragma unroll
            for(int mi=0;mi<2;mi++)
                #pragma unroll
                for(int nj=0;nj<4;nj++){
                    int ni = nh*4+nj;
                    MMA_OP(acc[mi][ni], a_lo[mi].x, a_hi[mi].x, a_lo[mi].y, a_hi[mi].y,
                                        bf[nj].x, bf[nj].y);
                    MMA_OP(acc[mi][ni], a_lo[mi].z, a_hi[mi].z, a_lo[mi].w, a_hi[mi].w,
                                        bf[nj].z, bf[nj].w);
                }
        }

        if(kb+2 < NK){
            int st = kb+2; int s2 = st - (st/3)*3;
            unsigned bo = (unsigned)(s2*8192);
            int ko = st*16;
            cpasync16(sbA + bo + off0, gA0 + ko);
            cpasync16(sbA + bo + off1, gA1 + ko);
            cpasync16(sbB + bo + off0, gB0 + ko);
            cpasync16(sbB + bo + off1, gB1 + ko);
        }
        asm volatile("cp.async.commit_group;" ::: "memory");
        asm volatile("cp.async.wait_group 1;" ::: "memory");
        __syncthreads();
        s++; if(s==3) s=0;
    }

    int c0 = (bx*128)/NID;   // first camera covered by this col-tile (<=2 total)
    if(!rankmode){
        #pragma unroll
        for(int mi=0;mi<2;mi++){
            float se[2][2] = {{0.0f,0.0f},{0.0f,0.0f}};
            #pragma unroll
            for(int ni=0;ni<8;ni++){
                int colb = bx*128 + n0 + ni*8 + tig*2;
                #pragma unroll
                for(int q=0;q<2;q++){
                    int gc = colb + q;
                    if(gc < CN){
                        int slot = (gc/NID) - c0;
                        se[0][slot] += __expf(acc[mi][ni][q]);
                        se[1][slot] += __expf(acc[mi][ni][2+q]);
                    }
                }
            }
            #pragma unroll
            for(int rh=0;rh<2;rh++)
                #pragma unroll
                for(int s2=0;s2<2;s2++){
                    float v = se[rh][s2];
                    v += __shfl_xor_sync(0xffffffffu, v, 1);
                    v += __shfl_xor_sync(0xffffffffu, v, 2);
                    se[rh][s2] = v;
                }
            if(tig == 0){
                int row = by*128 + m0 + mi*16 + g;
                #pragma unroll
                for(int rh=0;rh<2;rh++){
                    int b = row + rh*8;
                    #pragma unroll
                    for(int s2=0;s2<2;s2++){
                        int c = c0 + s2;
                        if(c < NCAM && se[rh][s2] != 0.0f)
                            atomicAdd(&g_sumZ[b*NCAM + c], se[rh][s2]);
                    }
                }
            }
        }
    } else {
        #pragma unroll
        for(int mi=0;mi<2;mi++){
            unsigned long long best[2][2] = {{0ull,0ull},{0ull,0ull}};
            #pragma unroll
            for(int ni=0;ni<8;ni++){
                int colb = bx*128 + n0 + ni*8 + tig*2;
                #pragma unroll
                for(int q=0;q<2;q++){
                    int gc = colb + q;
                    if(gc < CN){
                        int c = gc/NID, m = gc - c*NID;
                        int slot = (c==c0) ? 0 : 1;
                        unsigned long long k0 =
                            ((unsigned long long)fenc(acc[mi][ni][q])<<32)
                          | (unsigned)(0xFFFFFFFFu - (unsigned)m);
                        unsigned long long k1 =
                            ((unsigned long long)fenc(acc[mi][ni][2+q])<<32)
                          | (unsigned)(0xFFFFFFFFu - (unsigned)m);
                        if(k0 > best[0][slot]) best[0][slot] = k0;
                        if(k1 > best[1][slot]) best[1][slot] = k1;
                    }
                }
            }
            #pragma unroll
            for(int rh=0;rh<2;rh++)
                #pragma unroll
                for(int slot=0;slot<2;slot++){
                    unsigned long long v = best[rh][slot];
                    #pragma unroll
                    for(int o=1;o<4;o<<=1){
                        unsigned long long u = __shfl_xor_sync(0xffffffffu, v, o);
                        if(u > v) v = u;
                    }
                    best[rh][slot] = v;
                }
            if(tig == 0){
                int row0 = m0 + mi*16 + g;
                #pragma unroll
                for(int rh=0;rh<2;rh++){
                    int b = (by-4)*128 + row0 + rh*8;
                    #pragma unroll
                    for(int slot=0;slot<2;slot++){
                        int c = c0 + slot;
                        if(c < NCAM && best[rh][slot])
                            atomicMax(&g_rank_key[b*NCAM + c], best[rh][slot]);
                    }
                }
            }
        }
    }
}

// ---------------- rank extract + filtered task build (merged) ---------------
__global__ void k_rank_tasks(){
    int t = blockIdx.x*256 + threadIdx.x;
    if(t >= BC) return;
    unsigned long long key = g_rank_key[t];
    int   ridx = (int)(0xFFFFFFFFu - (unsigned)(key & 0xFFFFFFFFull));
    float sc   = fdec((unsigned)(key>>32));
    g_rank_idx[t] = ridx;
    g_score[t]    = sc;
    int b = t/NCAM, c = t - b*NCAM;
    int cam = g_cam[b];
    if(c != cam && sc > 0.5f){
        int pos = atomicAdd(&g_cnt[cam], 1);
        g_tasks[cam*BC + pos] = t;
    }
}

// ---------------- back GEMM (bf16 unpack + FFMA; normally empty) ------------
__global__ __launch_bounds__(256) void k_gemm_back(){
    __shared__ unsigned As2[8][132];
    __shared__ unsigned Bs2[8][132];
    __shared__ const unsigned* Arow[128];
    __shared__ const unsigned* Brow[128];
    __shared__ int Btask[128];
    __shared__ unsigned long long sred[128];

    int icam = blockIdx.z;
    int cnt  = g_cnt[icam];
    int tb   = blockIdx.y*128;
    if(tb >= cnt) return;
    int rb   = blockIdx.x*128;

    int tid = threadIdx.x;
    if(tid < 128){
        int n = rb + tid; if(n > NID-1) n = NID-1;
        Arow[tid] = g_Ah + (size_t)(icam*NID + n)*D2;
        sred[tid] = 0ull;
    } else {
        int k = tid-128;
        int tt = tb + k;
        int tcl = (tt < cnt) ? tt : (cnt-1);
        int t = g_tasks[icam*BC + tcl];
        Btask[k] = (tt < cnt) ? t : -1;
        int c = t % NCAM;
        Brow[k] = g_Ah + (size_t)(c*NID + g_rank_idx[t])*D2;
    }
    __syncthreads();

    int lr = tid>>1, h = tid&1;
    const unsigned* ap = Arow[lr] + h*4;
    const unsigned* bp = Brow[lr] + h*4;
    int tx = tid&15, ty = tid>>4;

    float acc[8][8];
    #pragma unroll
    for(int i=0;i<8;i++)
        #pragma unroll
        for(int j=0;j<8;j++) acc[i][j]=0.0f;

    for(int k0=0;k0<D2;k0+=8){
        uint4 av = *(const uint4*)(ap + k0);
        uint4 bv = *(const uint4*)(bp + k0);
        __syncthreads();
        As2[h*4+0][lr]=av.x; As2[h*4+1][lr]=av.y; As2[h*4+2][lr]=av.z; As2[h*4+3][lr]=av.w;
        Bs2[h*4+0][lr]=bv.x; Bs2[h*4+1][lr]=bv.y; Bs2[h*4+2][lr]=bv.z; Bs2[h*4+3][lr]=bv.w;
        __syncthreads();
        #pragma unroll
        for(int kk=0;kk<8;kk++){
            float2 a2[8], b2[8];
            #pragma unroll
            for(int i=0;i<4;i++){
                a2[i]   = __bfloat1622float2(*(__nv_bfloat162*)&As2[kk][ty*4+i]);
                a2[i+4] = __bfloat1622float2(*(__nv_bfloat162*)&As2[kk][64+ty*4+i]);
                b2[i]   = __bfloat1622float2(*(__nv_bfloat162*)&Bs2[kk][tx*4+i]);
                b2[i+4] = __bfloat1622float2(*(__nv_bfloat162*)&Bs2[kk][64+tx*4+i]);
            }
            #pragma unroll
            for(int i=0;i<8;i++)
                #pragma unroll
                for(int j=0;j<8;j++)
                    acc[i][j] += a2[i].x*b2[j].x + a2[i].y*b2[j].y;
        }
    }

    int rows[8], cols[8];
    #pragma unroll
    for(int i=0;i<4;i++){ rows[i]=ty*4+i; rows[i+4]=64+ty*4+i; }
    #pragma unroll
    for(int j=0;j<4;j++){ cols[j]=tx*4+j; cols[j+4]=64+tx*4+j; }

    #pragma unroll
    for(int j=0;j<8;j++){
        unsigned long long best = 0ull;
        #pragma unroll
        for(int i=0;i<8;i++){
            int n = rb + rows[i];
            if(n < NID){
                unsigned long long key = ((unsigned long long)fenc(acc[i][j])<<32)
                                       | (unsigned)(0xFFFFFFFFu - (unsigned)n);
                if(key > best) best = key;
            }
        }
        if(best) atomicMax(&sred[cols[j]], best);
    }
    __syncthreads();
    if(tid < 128){
        int t = Btask[tid];
        if(t >= 0 && sred[tid]) atomicMax(&g_back_key[t], sred[tid]);
    }
}

// ---------------- coef + loss + scatter + final out[0] (fully fused) --------
// warp per (b,c). At most ONE dot needed: self -> logit(cam,lab);
// valid cross -> logit(c,rank). Non-self non-valid contributes nothing.
__global__ __launch_bounds__(256) void k_coef(const void* epp, const void* lrp,
                                              float* __restrict__ out){
    int wid = threadIdx.x >> 5, lane = threadIdx.x & 31;
    int t = blockIdx.x*8 + wid;
    int ep = scal_int(epp);

    if(ep > 10 && t < BC){
        int b = t/NCAM, c = t - b*NCAM;
        int cam = g_cam[b], lab = g_lab[b];
        bool self = (c == cam);
        float sc = g_score[t];
        int backi = (int)(0xFFFFFFFFu - (unsigned)(g_back_key[t] & 0xFFFFFFFFull));
        bool valid = (!self) && (sc > 0.5f) && (backi == lab);
        if(self || valid){
            int row = self ? (cam*NID + lab) : (c*NID + g_rank_idx[t]);
            const uint4* fb = (const uint4*)(g_Fh + (size_t)b*D2);
            const uint4* ab = (const uint4*)(g_Ah + (size_t)row*D2);
            float d = 0.0f;
            #pragma unroll
            for(int j=0;j<8;j++){
                uint4 fv = fb[j*32+lane], av = ab[j*32+lane];
                #pragma unroll
                for(int w2=0;w2<4;w2++){
                    unsigned fw=(&fv.x)[w2], aw=(&av.x)[w2];
                    float2 f2=__bfloat1622float2(*(__nv_bfloat162*)&fw);
                    float2 a2=__bfloat1622float2(*(__nv_bfloat162*)&aw);
                    d += f2.x*a2.x + f2.y*a2.y;
                }
            }
            #pragma unroll
            for(int o=16;o;o>>=1) d += __shfl_xor_sync(0xffffffffu,d,o);
            float lrf = scal_float(lrp);
            float ce = logf(g_sumZ[t]) - d;
            float wgt = self ? 1.0f : sc;
            float coef = wgt * lrf * (1.0f - ce);
            if(lane == 0) atomicAdd(&g_loss, wgt*ce);
            if(coef != 0.0f){
                const float* f = g_F + (size_t)b*DIM;
                float* dst = out + 1 + (size_t)row*DIM;
                for(int dd = lane; dd < DIM; dd += 32)
                    atomicAdd(&dst[dd], -coef * f[dd]);
            }
        }
    }
    // completion ticket: last warp (of BC total) writes out[0]
    if(lane == 0){
        __threadfence();
        unsigned old = atomicAdd(&g_done, 1u);
        if(old == (unsigned)(BC - 1)){
            __threadfence();
            float l = *((volatile float*)&g_loss);
            out[0] = (ep > 10) ? (l / (float)BATCH) : 0.0f;
            g_done = 0u;   // self-reset for next replay
        }
    }
}

// ---------------- launch ----------------------------------------------------
extern "C" void kernel_launch(void* const* d_in, const int* in_sizes, int n_in,
                              void* d_out, int out_size){
    const float* features = (const float*)d_in[0];
    const int*   labels   = (const int*)  d_in[1];
    const int*   cams     = (const int*)  d_in[2];
    const float* intra    = (const float*)d_in[3];
    const float* cross    = (const float*)d_in[4];
    const void*  epp      = d_in[5];
    const void*  lrp      = d_in[6];
    float* out = (float*)d_out;

    k_norm_feat<<<BATCH, 256>>>(features, labels, cams);
    k_norm_cross<<<CN, 256>>>(cross, intra, epp, out);

    k_gemm_main<<<dim3(36, 8), 256>>>();
    k_rank_tasks<<<(BC+255)/256, 256>>>();
    k_gemm_back<<<dim3(6, 24, NCAM), 256>>>();

    k_coef<<<BC/8, 256>>>(epp, lrp, out);
}

// round 12
// speedup vs baseline: 1.2488x; 1.2488x over previous
#include <cuda_runtime.h>
#include <cuda_bf16.h>
#include <math.h>

#define BATCH 512
#define NCAM  6
#define NID   751
#define DIM   2048
#define D2    (DIM/2)       /* 1024 packed bf16x2 words per row */
#define CN    (NCAM*NID)    /* 4506 */
#define BC    (BATCH*NCAM)  /* 3072 */
#define NK    (D2/16)       /* 64 k-blocks of 16 words (32 halves) */

// ---------------- scratch (device globals; no allocation allowed) ----------
__device__ float    g_F[BATCH*DIM];       // normalized features (fp32, scatter)
__device__ unsigned g_Fh[BATCH*D2];       // packed bf16x2, K-permuted
__device__ unsigned g_Ah[CN*D2];          // packed bf16x2, K-permuted
__device__ float    g_sumZ[BC];           // sum exp(logits) per (b,cam)
__device__ unsigned long long g_rank_key[BC];
__device__ unsigned long long g_back_key[BC];
__device__ int      g_rank_idx[BC];
__device__ float    g_score[BC];
__device__ float    g_coef_cross[BC];
__device__ float    g_coef_self[BATCH];
__device__ int      g_qidx[BATCH];
__device__ int      g_cam[BATCH];
__device__ int      g_lab[BATCH];
__device__ int      g_tasks[NCAM*BC];
__device__ int      g_cnt[NCAM];
__device__ float    g_loss;

// ---------------- helpers --------------------------------------------------
__device__ __forceinline__ unsigned fenc(float f){
    unsigned u = __float_as_uint(f);
    return (u & 0x80000000u) ? ~u : (u | 0x80000000u);
}
__device__ __forceinline__ float fdec(unsigned e){
    unsigned u = (e & 0x80000000u) ? (e ^ 0x80000000u) : ~e;
    return __uint_as_float(u);
}
__device__ __forceinline__ int scal_int(const void* p){
    int v = *(const int*)p;
    if (v > -1000000 && v < 1000000) return v;
    return (int)(*(const float*)p);
}
__device__ __forceinline__ float scal_float(const void* p){
    int v = *(const int*)p;
    if (v > -1000000 && v < 1000000) return (float)v;
    return *(const float*)p;
}
__device__ __forceinline__ unsigned pack_bf2(float x, float y){
    __nv_bfloat162 h = __floats2bfloat162_rn(x, y);
    return *(unsigned*)&h;
}
// K-permutation inside each 16-word chunk: fragment words contiguous per thread
__device__ __forceinline__ int permk2(int K){
    return (K & ~15) | ((K & 3) << 2) | ((K >> 2) & 3);
}
__device__ __forceinline__ void cpasync16(unsigned saddr, const void* g){
    asm volatile("cp.async.cg.shared.global [%0], [%1], 16;" :: "r"(saddr), "l"(g));
}

// ---------------- feature norm + setup (fused) ------------------------------
__global__ __launch_bounds__(256) void k_norm_feat(const float* __restrict__ in,
                                                   const int* __restrict__ labels,
                                                   const int* __restrict__ cams){
    int row = blockIdx.x;
    int tid = threadIdx.x;
    int gi = row*256 + tid;
    if(gi < BC){ g_rank_key[gi]=0ull; g_back_key[gi]=0ull; g_sumZ[gi]=0.0f; }
    if(gi < NCAM) g_cnt[gi]=0;
    if(gi == 0) g_loss = 0.0f;
    if(gi < BATCH){
        int cam = cams[gi]-1, lab = labels[gi]-1;
        g_cam[gi]=cam; g_lab[gi]=lab;
        g_qidx[gi]=cam*NID+lab;
    }
    const float4* ip = (const float4*)(in + (size_t)row*DIM);
    float4 a = ip[tid], b = ip[tid+256];
    float ss = a.x*a.x+a.y*a.y+a.z*a.z+a.w*a.w
             + b.x*b.x+b.y*b.y+b.z*b.z+b.w*b.w;
    __shared__ float red[8];
    #pragma unroll
    for(int o=16;o;o>>=1) ss += __shfl_xor_sync(0xffffffffu, ss, o);
    if((tid&31)==0) red[tid>>5]=ss;
    __syncthreads();
    float tot = red[0]+red[1]+red[2]+red[3]+red[4]+red[5]+red[6]+red[7];
    float s = 1.0f/(sqrtf(tot)+1e-12f);
    a.x*=s;a.y*=s;a.z*=s;a.w*=s; b.x*=s;b.y*=s;b.z*=s;b.w*=s;
    float4* op = (float4*)(g_F + (size_t)row*DIM);
    op[tid]=a; op[tid+256]=b;
    unsigned* hp = g_Fh + (size_t)row*D2;
    hp[permk2(2*tid  )]     = pack_bf2(a.x,a.y);
    hp[permk2(2*tid+1)]     = pack_bf2(a.z,a.w);
    hp[permk2(512+2*tid  )] = pack_bf2(b.x,b.y);
    hp[permk2(512+2*tid+1)] = pack_bf2(b.z,b.w);
}

// cross/intra anchors: packed bf16 + output base (fused warm path)
__global__ __launch_bounds__(256) void k_norm_cross(const float* __restrict__ cross,
                                                    const float* __restrict__ intra,
                                                    const void* epp,
                                                    float* __restrict__ out){
    int row = blockIdx.x;
    int tid = threadIdx.x;
    bool warm = (scal_int(epp) <= 10);
    const float* in = warm ? intra : cross;
    const float4* ip = (const float4*)(in + (size_t)row*DIM);
    float4 a = ip[tid], b = ip[tid+256];
    float ss = a.x*a.x+a.y*a.y+a.z*a.z+a.w*a.w
             + b.x*b.x+b.y*b.y+b.z*b.z+b.w*b.w;
    __shared__ float red[8];
    #pragma unroll
    for(int o=16;o;o>>=1) ss += __shfl_xor_sync(0xffffffffu, ss, o);
    if((tid&31)==0) red[tid>>5]=ss;
    __syncthreads();
    float tot = red[0]+red[1]+red[2]+red[3]+red[4]+red[5]+red[6]+red[7];
    float s = 1.0f/(sqrtf(tot)+1e-12f);
    a.x*=s;a.y*=s;a.z*=s;a.w*=s; b.x*=s;b.y*=s;b.z*=s;b.w*=s;
    unsigned* hp = g_Ah + (size_t)row*D2;
    hp[permk2(2*tid  )]     = pack_bf2(a.x,a.y);
    hp[permk2(2*tid+1)]     = pack_bf2(a.z,a.w);
    hp[permk2(512+2*tid  )] = pack_bf2(b.x,b.y);
    hp[permk2(512+2*tid+1)] = pack_bf2(b.z,b.w);
    // out+1 is only 4B aligned -> scalar stores
    float* dst = out + 1 + (size_t)row*DIM;
    dst[tid*4+0]=a.x; dst[tid*4+1]=a.y; dst[tid*4+2]=a.z; dst[tid*4+3]=a.w;
    dst[1024+tid*4+0]=b.x; dst[1024+tid*4+1]=b.y; dst[1024+tid*4+2]=b.z; dst[1024+tid*4+3]=b.w;
}

// ---------------- main GEMM (bf16 mma, 3-stage cp.async pipeline) -----------
// logits CTAs (by<4) fold sum-exp directly (logits in [-1,1]: no max needed);
// rank CTAs (by>=4) fold argmax keys. Logits never materialized.
#define MMA_OP(ACC,A0,A1,A2,A3,B0,B1) \
    asm volatile("mma.sync.aligned.m16n8k16.row.col.f32.bf16.bf16.f32 " \
        "{%0,%1,%2,%3}, {%4,%5,%6,%7}, {%8,%9}, {%0,%1,%2,%3};" \
        : "+f"((ACC)[0]), "+f"((ACC)[1]), "+f"((ACC)[2]), "+f"((ACC)[3]) \
        : "r"(A0),"r"(A1),"r"(A2),"r"(A3),"r"(B0),"r"(B1))

__global__ __launch_bounds__(256,2) void k_gemm_main(){
    __shared__ unsigned As[3][2048];    // [stage][row*16 + word]
    __shared__ unsigned Bs[3][2048];

    int tid=threadIdx.x, bx=blockIdx.x, by=blockIdx.y;
    bool rankmode = (by >= 4);

    int lane = tid & 31, w = tid >> 5;
    int wm = w >> 1, wn = w & 1;
    int g = lane >> 2, tig = lane & 3;
    int m0 = wm*32, n0 = wn*64;

    // per-thread prefetch lanes: 2 A rows + 2 B rows, one 16B seg each
    int prow = tid >> 2, pseg = tid & 3;
    int ar0 = by*128 + prow;
    const unsigned* gA0 = (rankmode ? (g_Ah + (size_t)g_qidx[ar0-512]*D2)
                                    : (g_Fh + (size_t)ar0*D2)) + pseg*4;
    const unsigned* gA1 = (rankmode ? (g_Ah + (size_t)g_qidx[ar0-512+64]*D2)
                                    : (g_Fh + (size_t)(ar0+64)*D2)) + pseg*4;
    int cb0 = bx*128 + prow;      int cc0 = (cb0 < CN) ? cb0 : (CN-1);
    int cb1 = cb0 + 64;           int cc1 = (cb1 < CN) ? cb1 : (CN-1);
    const unsigned* gB0 = g_Ah + (size_t)cc0*D2 + pseg*4;
    const unsigned* gB1 = g_Ah + (size_t)cc1*D2 + pseg*4;
    unsigned off0 = (unsigned)((prow*16 + pseg*4)*4);
    unsigned off1 = (unsigned)(((prow+64)*16 + pseg*4)*4);
    unsigned sbA = (unsigned)__cvta_generic_to_shared(&As[0][0]);
    unsigned sbB = (unsigned)__cvta_generic_to_shared(&Bs[0][0]);

    float acc[2][8][4];
    #pragma unroll
    for(int mi=0;mi<2;mi++)
        #pragma unroll
        for(int ni=0;ni<8;ni++)
            #pragma unroll
            for(int q=0;q<4;q++) acc[mi][ni][q]=0.0f;

    // prefetch stages 0 and 1
    #pragma unroll
    for(int st=0; st<2; st++){
        unsigned bo = (unsigned)(st*8192);
        int ko = st*16;
        cpasync16(sbA + bo + off0, gA0 + ko);
        cpasync16(sbA + bo + off1, gA1 + ko);
        cpasync16(sbB + bo + off0, gB0 + ko);
        cpasync16(sbB + bo + off1, gB1 + ko);
        asm volatile("cp.async.commit_group;" ::: "memory");
    }
    asm volatile("cp.async.wait_group 1;" ::: "memory");
    __syncthreads();

    int s = 0;
    for(int kb=0; kb<NK; kb++){
        const unsigned* as  = As[s];
        const unsigned* bsp = Bs[s];

        uint4 a_lo[2], a_hi[2];
        #pragma unroll
        for(int mi=0;mi<2;mi++){
            a_lo[mi] = *(const uint4*)(as + (m0 + mi*16 + g)*16 + tig*4);
            a_hi[mi] = *(const uint4*)(as + (m0 + mi*16 + 8 + g)*16 + tig*4);
        }
        #pragma unroll
        for(int nh=0; nh<2; nh++){
            uint4 bf[4];
            #pragma unroll
            for(int nj=0;nj<4;nj++)
                bf[nj] = *(const uint4*)(bsp + (n0 + (nh*4+nj)*8 + g)*16 + tig*4);
            #pragma unroll
            for(int mi=0;mi<2;mi++)
                #pragma unroll
                for(int nj=0;nj<4;nj++){
                    int ni = nh*4+nj;
                    MMA_OP(acc[mi][ni], a_lo[mi].x, a_hi[mi].x, a_lo[mi].y, a_hi[mi].y,
                                        bf[nj].x, bf[nj].y);
                    MMA_OP(acc[mi][ni], a_lo[mi].z, a_hi[mi].z, a_lo[mi].w, a_hi[mi].w,
                                        bf[nj].z, bf[nj].w);
                }
        }

        if(kb+2 < NK){
            int st = kb+2; int s2 = st - (st/3)*3;
            unsigned bo = (unsigned)(s2*8192);
            int ko = st*16;
            cpasync16(sbA + bo + off0, gA0 + ko);
            cpasync16(sbA + bo + off1, gA1 + ko);
            cpasync16(sbB + bo + off0, gB0 + ko);
            cpasync16(sbB + bo + off1, gB1 + ko);
        }
        asm volatile("cp.async.commit_group;" ::: "memory");
        asm volatile("cp.async.wait_group 1;" ::: "memory");
        __syncthreads();
        s++; if(s==3) s=0;
    }

    int c0 = (bx*128)/NID;   // first camera covered by this col-tile (<=2 total)
    if(!rankmode){
        #pragma unroll
        for(int mi=0;mi<2;mi++){
            float se[2][2] = {{0.0f,0.0f},{0.0f,0.0f}};
            #pragma unroll
            for(int ni=0;ni<8;ni++){
                int colb = bx*128 + n0 + ni*8 + tig*2;
                #pragma unroll
                for(int q=0;q<2;q++){
                    int gc = colb + q;
                    if(gc < CN){
                        int slot = (gc/NID) - c0;
                        se[0][slot] += __expf(acc[mi][ni][q]);
                        se[1][slot] += __expf(acc[mi][ni][2+q]);
                    }
                }
            }
            #pragma unroll
            for(int rh=0;rh<2;rh++)
                #pragma unroll
                for(int s2=0;s2<2;s2++){
                    float v = se[rh][s2];
                    v += __shfl_xor_sync(0xffffffffu, v, 1);
                    v += __shfl_xor_sync(0xffffffffu, v, 2);
                    se[rh][s2] = v;
                }
            if(tig == 0){
                int row = by*128 + m0 + mi*16 + g;
                #pragma unroll
                for(int rh=0;rh<2;rh++){
                    int b = row + rh*8;
                    #pragma unroll
                    for(int s2=0;s2<2;s2++){
                        int c = c0 + s2;
                        if(c < NCAM && se[rh][s2] != 0.0f)
                            atomicAdd(&g_sumZ[b*NCAM + c], se[rh][s2]);
                    }
                }
            }
        }
    } else {
        #pragma unroll
        for(int mi=0;mi<2;mi++){
            unsigned long long best[2][2] = {{0ull,0ull},{0ull,0ull}};
            #pragma unroll
            for(int ni=0;ni<8;ni++){
                int colb = bx*128 + n0 + ni*8 + tig*2;
                #pragma unroll
                for(int q=0;q<2;q++){
                    int gc = colb + q;
                    if(gc < CN){
                        int c = gc/NID, m = gc - c*NID;
                        int slot = (c==c0) ? 0 : 1;
                        unsigned long long k0 =
                            ((unsigned long long)fenc(acc[mi][ni][q])<<32)
                          | (unsigned)(0xFFFFFFFFu - (unsigned)m);
                        unsigned long long k1 =
                            ((unsigned long long)fenc(acc[mi][ni][2+q])<<32)
                          | (unsigned)(0xFFFFFFFFu - (unsigned)m);
                        if(k0 > best[0][slot]) best[0][slot] = k0;
                        if(k1 > best[1][slot]) best[1][slot] = k1;
                    }
                }
            }
            #pragma unroll
            for(int rh=0;rh<2;rh++)
                #pragma unroll
                for(int slot=0;slot<2;slot++){
                    unsigned long long v = best[rh][slot];
                    #pragma unroll
                    for(int o=1;o<4;o<<=1){
                        unsigned long long u = __shfl_xor_sync(0xffffffffu, v, o);
                        if(u > v) v = u;
                    }
                    best[rh][slot] = v;
                }
            if(tig == 0){
                int row0 = m0 + mi*16 + g;
                #pragma unroll
                for(int rh=0;rh<2;rh++){
                    int b = (by-4)*128 + row0 + rh*8;
                    #pragma unroll
                    for(int slot=0;slot<2;slot++){
                        int c = c0 + slot;
                        if(c < NCAM && best[rh][slot])
                            atomicMax(&g_rank_key[b*NCAM + c], best[rh][slot]);
                    }
                }
            }
        }
    }
}

// ---------------- rank extract + filtered task build (merged) ---------------
__global__ void k_rank_tasks(){
    int t = blockIdx.x*256 + threadIdx.x;
    if(t >= BC) return;
    unsigned long long key = g_rank_key[t];
    int   ridx = (int)(0xFFFFFFFFu - (unsigned)(key & 0xFFFFFFFFull));
    float sc   = fdec((unsigned)(key>>32));
    g_rank_idx[t] = ridx;
    g_score[t]    = sc;
    int b = t/NCAM, c = t - b*NCAM;
    int cam = g_cam[b];
    if(c != cam && sc > 0.5f){
        int pos = atomicAdd(&g_cnt[cam], 1);
        g_tasks[cam*BC + pos] = t;
    }
}

// ---------------- back GEMM (bf16 unpack + FFMA; normally empty) ------------
__global__ __launch_bounds__(256) void k_gemm_back(){
    __shared__ unsigned As2[8][132];
    __shared__ unsigned Bs2[8][132];
    __shared__ const unsigned* Arow[128];
    __shared__ const unsigned* Brow[128];
    __shared__ int Btask[128];
    __shared__ unsigned long long sred[128];

    int icam = blockIdx.z;
    int cnt  = g_cnt[icam];
    int tb   = blockIdx.y*128;
    if(tb >= cnt) return;
    int rb   = blockIdx.x*128;

    int tid = threadIdx.x;
    if(tid < 128){
        int n = rb + tid; if(n > NID-1) n = NID-1;
        Arow[tid] = g_Ah + (size_t)(icam*NID + n)*D2;
        sred[tid] = 0ull;
    } else {
        int k = tid-128;
        int tt = tb + k;
        int tcl = (tt < cnt) ? tt : (cnt-1);
        int t = g_tasks[icam*BC + tcl];
        Btask[k] = (tt < cnt) ? t : -1;
        int c = t % NCAM;
        Brow[k] = g_Ah + (size_t)(c*NID + g_rank_idx[t])*D2;
    }
    __syncthreads();

    int lr = tid>>1, h = tid&1;
    const unsigned* ap = Arow[lr] + h*4;
    const unsigned* bp = Brow[lr] + h*4;
    int tx = tid&15, ty = tid>>4;

    float acc[8][8];
    #pragma unroll
    for(int i=0;i<8;i++)
        #pragma unroll
        for(int j=0;j<8;j++) acc[i][j]=0.0f;

    for(int k0=0;k0<D2;k0+=8){
        uint4 av = *(const uint4*)(ap + k0);
        uint4 bv = *(const uint4*)(bp + k0);
        __syncthreads();
        As2[h*4+0][lr]=av.x; As2[h*4+1][lr]=av.y; As2[h*4+2][lr]=av.z; As2[h*4+3][lr]=av.w;
        Bs2[h*4+0][lr]=bv.x; Bs2[h*4+1][lr]=bv.y; Bs2[h*4+2][lr]=bv.z; Bs2[h*4+3][lr]=bv.w;
        __syncthreads();
        #pragma unroll
        for(int kk=0;kk<8;kk++){
            float2 a2[8], b2[8];
            #pragma unroll
            for(int i=0;i<4;i++){
                a2[i]   = __bfloat1622float2(*(__nv_bfloat162*)&As2[kk][ty*4+i]);
                a2[i+4] = __bfloat1622float2(*(__nv_bfloat162*)&As2[kk][64+ty*4+i]);
                b2[i]   = __bfloat1622float2(*(__nv_bfloat162*)&Bs2[kk][tx*4+i]);
                b2[i+4] = __bfloat1622float2(*(__nv_bfloat162*)&Bs2[kk][64+tx*4+i]);
            }
            #pragma unroll
            for(int i=0;i<8;i++)
                #pragma unroll
                for(int j=0;j<8;j++)
                    acc[i][j] += a2[i].x*b2[j].x + a2[i].y*b2[j].y;
        }
    }

    int rows[8], cols[8];
    #pragma unroll
    for(int i=0;i<4;i++){ rows[i]=ty*4+i; rows[i+4]=64+ty*4+i; }
    #pragma unroll
    for(int j=0;j<4;j++){ cols[j]=tx*4+j; cols[j+4]=64+tx*4+j; }

    #pragma unroll
    for(int j=0;j<8;j++){
        unsigned long long best = 0ull;
        #pragma unroll
        for(int i=0;i<8;i++){
            int n = rb + rows[i];
            if(n < NID){
                unsigned long long key = ((unsigned long long)fenc(acc[i][j])<<32)
                                       | (unsigned)(0xFFFFFFFFu - (unsigned)n);
                if(key > best) best = key;
            }
        }
        if(best) atomicMax(&sred[cols[j]], best);
    }
    __syncthreads();
    if(tid < 128){
        int t = Btask[tid];
        if(t >= 0 && sred[tid]) atomicMax(&g_back_key[t], sred[tid]);
    }
}

// ---------------- coefficients + loss (single dot per (b,c) at most) --------
// self -> needs logit(cam,lab); valid cross -> needs logit(c,rank);
// non-self non-valid -> coef 0, no dot, no loss term.
__global__ __launch_bounds__(256) void k_coef(const void* lrp){
    int wid = threadIdx.x >> 5, lane = threadIdx.x & 31;
    int t = blockIdx.x*8 + wid;
    if(t >= BC) return;
    int b = t/NCAM, c = t - b*NCAM;
    int cam = g_cam[b], lab = g_lab[b];
    bool self = (c == cam);
    float sc = g_score[t];
    int backi = (int)(0xFFFFFFFFu - (unsigned)(g_back_key[t] & 0xFFFFFFFFull));
    bool valid = (!self) && (sc > 0.5f) && (backi == lab);

    if(!(self || valid)){
        if(lane == 0) g_coef_cross[t] = 0.0f;
        return;
    }
    int row = self ? (cam*NID + lab) : (c*NID + g_rank_idx[t]);
    const uint4* fb = (const uint4*)(g_Fh + (size_t)b*D2);
    const uint4* ab = (const uint4*)(g_Ah + (size_t)row*D2);
    float d = 0.0f;
    #pragma unroll
    for(int j=0;j<8;j++){
        uint4 fv = fb[j*32+lane], av = ab[j*32+lane];
        #pragma unroll
        for(int w2=0;w2<4;w2++){
            unsigned fw=(&fv.x)[w2], aw=(&av.x)[w2];
            float2 f2=__bfloat1622float2(*(__nv_bfloat162*)&fw);
            float2 a2=__bfloat1622float2(*(__nv_bfloat162*)&aw);
            d += f2.x*a2.x + f2.y*a2.y;
        }
    }
    #pragma unroll
    for(int o=16;o;o>>=1) d += __shfl_xor_sync(0xffffffffu,d,o);
    if(lane == 0){
        float lrf = scal_float(lrp);
        float ce = logf(g_sumZ[t]) - d;
        if(self){
            g_coef_cross[t] = 0.0f;
            g_coef_self[b]  = lrf * (1.0f - ce);
            atomicAdd(&g_loss, ce);
        } else {
            g_coef_cross[t] = sc * lrf * (1.0f - ce);
            atomicAdd(&g_loss, sc * ce);
        }
    }
}

// ---------------- scatter update -------------------------------------------
__global__ __launch_bounds__(256) void k_scatter(const void* epp, float* __restrict__ out){
    int ep = scal_int(epp);
    if(ep <= 10) return;
    int b = blockIdx.x, j = blockIdx.y;
    float coef; int row;
    if(j == NCAM){ coef = g_coef_self[b]; row = g_qidx[b]; }
    else { int t = b*NCAM + j; coef = g_coef_cross[t]; row = j*NID + g_rank_idx[t]; }
    if(coef == 0.0f) return;
    const float* f = g_F + (size_t)b*DIM;
    float* dst = out + 1 + (size_t)row*DIM;
    for(int d=threadIdx.x; d<DIM; d+=256)
        atomicAdd(&dst[d], -coef * f[d]);
}

__global__ void k_loss(const void* epp, float* out){
    int ep = scal_int(epp);
    out[0] = (ep > 10) ? (g_loss / (float)BATCH) : 0.0f;
}

// ---------------- launch ----------------------------------------------------
extern "C" void kernel_launch(void* const* d_in, const int* in_sizes, int n_in,
                              void* d_out, int out_size){
    const float* features = (const float*)d_in[0];
    const int*   labels   = (const int*)  d_in[1];
    const int*   cams     = (const int*)  d_in[2];
    const float* intra    = (const float*)d_in[3];
    const float* cross    = (const float*)d_in[4];
    const void*  epp      = d_in[5];
    const void*  lrp      = d_in[6];
    float* out = (float*)d_out;

    k_norm_feat<<<BATCH, 256>>>(features, labels, cams);
    k_norm_cross<<<CN, 256>>>(cross, intra, epp, out);

    k_gemm_main<<<dim3(36, 8), 256>>>();
    k_rank_tasks<<<(BC+255)/256, 256>>>();
    k_gemm_back<<<dim3(6, 24, NCAM), 256>>>();

    k_coef<<<BC/8, 256>>>(lrp);

    k_scatter<<<dim3(BATCH, NCAM+1), 256>>>(epp, out);
    k_loss<<<1, 1>>>(epp, out);
}